// round 12
// baseline (speedup 1.0000x reference)
#include <cuda_runtime.h>
#include <cuda_bf16.h>
#include <cstdint>

typedef unsigned long long ull;

#define QL    2048
#define HISTL 2048
#define KLEN  4096
#define NH    12
#define NKVH  2
#define HD    128
#define HID   1536
#define GRP   6
#define K3    4608           // 3 * 1536 (hi/lo compensated K extension, GEMM)

// ---------------- scratch (static device globals; no allocation) ----------------
__device__ float g_q[QL * HID];          // Q projection (pre-RoPE, f32)
__device__ float g_kn[QL * NKVH * HD];   // new K projection (pre-RoPE)
__device__ float g_vn[QL * NKVH * HD];   // new V projection
__device__ float g_v[NKVH * KLEN * HD];  // full V (f32, for transpose)

// GEMM triplet operands (proven R7-R9 path)
__device__ __nv_bfloat16 g_x3[QL * K3];
__device__ __nv_bfloat16 g_w3[2048 * K3];
__device__ __nv_bfloat16 g_wo3[HID * K3];
__device__ __nv_bfloat16 g_at3[QL * K3];

// attention plane-split operands (hi / lo separate)
__device__ __nv_bfloat16 g_qh[NH * QL * HD];
__device__ __nv_bfloat16 g_qlo[NH * QL * HD];
__device__ __nv_bfloat16 g_kh[NKVH * KLEN * HD];
__device__ __nv_bfloat16 g_klo[NKVH * KLEN * HD];
__device__ __nv_bfloat16 g_vth[NKVH * HD * KLEN];   // V^T hi: [kv][d][pos]
__device__ __nv_bfloat16 g_vtl[NKVH * HD * KLEN];   // V^T lo

// ---------------- helpers ----------------
__device__ __forceinline__ uint32_t smem_u32(const void* p) {
    uint32_t a;
    asm("{ .reg .u64 t; cvta.to.shared.u64 t, %1; cvt.u32.u64 %0, t; }" : "=r"(a) : "l"(p));
    return a;
}
#define SWZ128(off) ((off) ^ (((off) >> 3) & 0x70))

__device__ __forceinline__ void ldsm4(uint32_t* r, uint32_t addr) {
    asm volatile("ldmatrix.sync.aligned.m8n8.x4.shared.b16 {%0,%1,%2,%3}, [%4];"
        : "=r"(r[0]), "=r"(r[1]), "=r"(r[2]), "=r"(r[3]) : "r"(addr));
}
__device__ __forceinline__ void mma16816(float* d, const uint32_t* a, const uint32_t* b) {
    asm volatile("mma.sync.aligned.m16n8k16.row.col.f32.bf16.bf16.f32 "
        "{%0,%1,%2,%3},{%4,%5,%6,%7},{%8,%9},{%0,%1,%2,%3};"
        : "+f"(d[0]), "+f"(d[1]), "+f"(d[2]), "+f"(d[3])
        : "r"(a[0]), "r"(a[1]), "r"(a[2]), "r"(a[3]), "r"(b[0]), "r"(b[1]));
}
__device__ __forceinline__ void cp_async16(uint32_t saddr, const void* gptr) {
    asm volatile("cp.async.cg.shared.global [%0], [%1], 16;"
        :: "r"(saddr), "l"((size_t)__cvta_generic_to_global(gptr)) : "memory");
}
__device__ __forceinline__ void cp_commit() { asm volatile("cp.async.commit_group;" ::: "memory"); }
__device__ __forceinline__ void cp_wait0()  { asm volatile("cp.async.wait_group 0;" ::: "memory"); }
__device__ __forceinline__ void cp_wait1()  { asm volatile("cp.async.wait_group 1;" ::: "memory"); }

__device__ __forceinline__ void split2(float v, __nv_bfloat16& h, __nv_bfloat16& l) {
    h = __float2bfloat16(v);
    l = __float2bfloat16(v - __bfloat162float(h));
}
__device__ __forceinline__ uint32_t bfpack(__nv_bfloat16 a, __nv_bfloat16 b) {
    return (uint32_t)__bfloat16_as_ushort(a) | ((uint32_t)__bfloat16_as_ushort(b) << 16);
}

// ================= conversion kernels =================
__global__ void conv_x3_kernel(const float* __restrict__ src) {
    const int i = blockIdx.x * blockDim.x + threadIdx.x;
    const int m = i / HID, k = i % HID;
    __nv_bfloat16 h, l;
    split2(src[i], h, l);
    __nv_bfloat16* p = g_x3 + (ull)m * K3 + 3 * k;
    p[0] = h; p[1] = h; p[2] = l;
}

__global__ void conv_wqkv3_kernel(const float* __restrict__ Wq,
                                  const float* __restrict__ Wk,
                                  const float* __restrict__ Wv) {
    __shared__ float t[32][33];
    const int n0 = blockIdx.x * 32, k0 = blockIdx.y * 32;
    const int tx = threadIdx.x, ty = threadIdx.y;
    const float* W; int nb, ld;
    if (n0 < 1536)      { W = Wq; nb = n0;        ld = HID; }
    else if (n0 < 1792) { W = Wk; nb = n0 - 1536; ld = NKVH * HD; }
    else                { W = Wv; nb = n0 - 1792; ld = NKVH * HD; }
    for (int r = ty; r < 32; r += 8)
        t[r][tx] = W[(ull)(k0 + r) * ld + nb + tx];
    __syncthreads();
    for (int r = ty; r < 32; r += 8) {
        __nv_bfloat16 h, l;
        split2(t[tx][r], h, l);
        __nv_bfloat16* p = g_w3 + (ull)(n0 + r) * K3 + 3 * (k0 + tx);
        p[0] = h; p[1] = l; p[2] = h;
    }
}

__global__ void conv_wo3_kernel(const float* __restrict__ Wo) {
    __shared__ float t[32][33];
    const int n0 = blockIdx.x * 32, k0 = blockIdx.y * 32;
    const int tx = threadIdx.x, ty = threadIdx.y;
    for (int r = ty; r < 32; r += 8)
        t[r][tx] = Wo[(ull)(k0 + r) * HID + n0 + tx];
    __syncthreads();
    for (int r = ty; r < 32; r += 8) {
        __nv_bfloat16 h, l;
        split2(t[tx][r], h, l);
        __nv_bfloat16* p = g_wo3 + (ull)(n0 + r) * K3 + 3 * (k0 + tx);
        p[0] = h; p[1] = l; p[2] = h;
    }
}

// ================= HMMA GEMM (proven, 3-stage cp.async) =================
#define CHK     64
#define NCHUNK  (K3 / CHK)          // 72
#define TILE_B  16384
#define NBUF    3
#define GEMM_SMEM (NBUF * 2 * TILE_B)

__global__ __launch_bounds__(256, 2) void hmma_gemm_kernel(
    int mode, float* __restrict__ outp,
    const float* __restrict__ bq, const float* __restrict__ bk, const float* __restrict__ bv)
{
    extern __shared__ __align__(1024) char dynsm[];
    const uint32_t sbase = smem_u32(dynsm);
    const int tid  = threadIdx.x;
    const int lane = tid & 31;
    const int wid  = tid >> 5;
    const int wm   = wid >> 2;
    const int wn   = wid & 3;
    const int m0   = blockIdx.y * 128;
    const int n0   = blockIdx.x * 128;

    const __nv_bfloat16* __restrict__ A3 = (mode == 0) ? g_x3 : g_at3;
    const __nv_bfloat16* __restrict__ B3 = (mode == 0) ? g_w3 : g_wo3;

    float d[4][4][4];
#pragma unroll
    for (int mi = 0; mi < 4; mi++)
#pragma unroll
        for (int ni = 0; ni < 4; ni++)
#pragma unroll
            for (int r = 0; r < 4; r++) d[mi][ni][r] = 0.f;

    const int lr = tid >> 3;
    const int lg = tid & 7;

#pragma unroll
    for (int pc = 0; pc < 2; pc++) {
        const uint32_t sA = sbase + pc * (2u * TILE_B), sB = sA + TILE_B;
        const int k0 = pc * CHK;
#pragma unroll
        for (int it = 0; it < 4; it++) {
            const int r = lr + it * 32;
            const uint32_t so = SWZ128((uint32_t)(r * 128 + lg * 16));
            cp_async16(sA + so, A3 + (ull)(m0 + r) * K3 + k0 + lg * 8);
            cp_async16(sB + so, B3 + (ull)(n0 + r) * K3 + k0 + lg * 8);
        }
        cp_commit();
    }

    const int arow = wm * 64 + (lane & 15);
    const int acol = (lane & 16) ? 16 : 0;
    const int brow = wn * 32 + (lane & 7) + ((lane & 16) ? 8 : 0);
    const int bcol = (lane & 8) ? 16 : 0;

    int ldbuf = 2;
    for (int c = 0; c < NCHUNK; c++) {
        cp_wait1();
        __syncthreads();
        if (c + 2 < NCHUNK) {
            const uint32_t sA = sbase + (uint32_t)ldbuf * (2u * TILE_B), sB = sA + TILE_B;
            const int k0 = (c + 2) * CHK;
#pragma unroll
            for (int it = 0; it < 4; it++) {
                const int r = lr + it * 32;
                const uint32_t so = SWZ128((uint32_t)(r * 128 + lg * 16));
                cp_async16(sA + so, A3 + (ull)(m0 + r) * K3 + k0 + lg * 8);
                cp_async16(sB + so, B3 + (ull)(n0 + r) * K3 + k0 + lg * 8);
            }
            cp_commit();
            if (++ldbuf == NBUF) ldbuf = 0;
        }
        const uint32_t cb = (uint32_t)(c % NBUF) * (2u * TILE_B);
        const uint32_t sA = sbase + cb, sB = sbase + cb + TILE_B;
#pragma unroll
        for (int kk = 0; kk < 4; kk++) {
            uint32_t a[4][4], bb[4][2];
#pragma unroll
            for (int mi = 0; mi < 4; mi++)
                ldsm4(a[mi], sA + SWZ128((uint32_t)((arow + mi * 16) * 128 + kk * 32 + acol)));
            {
                uint32_t t4[4];
                ldsm4(t4, sB + SWZ128((uint32_t)(brow * 128 + kk * 32 + bcol)));
                bb[0][0] = t4[0]; bb[0][1] = t4[1]; bb[1][0] = t4[2]; bb[1][1] = t4[3];
                ldsm4(t4, sB + SWZ128((uint32_t)((brow + 16) * 128 + kk * 32 + bcol)));
                bb[2][0] = t4[0]; bb[2][1] = t4[1]; bb[3][0] = t4[2]; bb[3][1] = t4[3];
            }
#pragma unroll
            for (int mi = 0; mi < 4; mi++)
#pragma unroll
                for (int ni = 0; ni < 4; ni++)
                    mma16816(d[mi][ni], a[mi], bb[ni]);
        }
        __syncthreads();
    }

    float* dst; int ldc; const float* bias; int coff;
    if (mode == 1)        { dst = outp; ldc = HID;       bias = nullptr;          coff = n0; }
    else if (n0 < 1536)   { dst = g_q;  ldc = HID;       bias = bq + n0;          coff = n0; }
    else if (n0 < 1792)   { dst = g_kn; ldc = NKVH * HD; bias = bk + (n0 - 1536); coff = n0 - 1536; }
    else                  { dst = g_vn; ldc = NKVH * HD; bias = bv + (n0 - 1792); coff = n0 - 1792; }

#pragma unroll
    for (int mi = 0; mi < 4; mi++) {
        const int r0 = m0 + wm * 64 + mi * 16 + (lane >> 2);
#pragma unroll
        for (int ni = 0; ni < 4; ni++) {
            const int cl = wn * 32 + ni * 8 + (lane & 3) * 2;
            float b0 = 0.f, b1 = 0.f;
            if (bias) { b0 = bias[cl]; b1 = bias[cl + 1]; }
            float2 v0 = { d[mi][ni][0] + b0, d[mi][ni][1] + b1 };
            float2 v1 = { d[mi][ni][2] + b0, d[mi][ni][3] + b1 };
            *(float2*)(dst + (ull)r0 * ldc + coff + cl)       = v0;
            *(float2*)(dst + (ull)(r0 + 8) * ldc + coff + cl) = v1;
        }
    }
}

// ---------------- RoPE on Q -> Qh/Ql planes ----------------
__global__ void rope_q_kernel(const float* __restrict__ fcos, const float* __restrict__ fsin)
{
    const int t = blockIdx.x;
    const int h = threadIdx.x >> 6;
    const int i = threadIdx.x & 63;
    const float* q = g_q + (ull)t * HID + h * HD;
    const float c = fcos[t * 64 + i];
    const float s = fsin[t * 64 + i];
    const float x1 = q[i];
    const float x2 = q[i + 64];
    const float r1 = x1 * c - x2 * s;
    const float r2 = x1 * s + x2 * c;
    __nv_bfloat16 h1, l1, h2, l2;
    split2(r1, h1, l1); split2(r2, h2, l2);
    const ull base = ((ull)h * QL + t) * HD;
    g_qh[base + i] = h1;       g_qlo[base + i] = l1;
    g_qh[base + i + 64] = h2;  g_qlo[base + i + 64] = l2;
}

// ---------------- build full K planes + V (f32) ----------------
__global__ void build_kv_kernel(
    const float* __restrict__ k_hist, const float* __restrict__ v_hist,
    const float* __restrict__ fcos, const float* __restrict__ fsin)
{
    const int pos = blockIdx.x;
    const int kv = blockIdx.y;
    const int i = threadIdx.x;
    float* vd = g_v + ((ull)(kv * KLEN + pos)) * HD;
    float k1, k2;
    if (pos < HISTL) {
        const float* ks = k_hist + ((ull)pos * NKVH + kv) * HD;
        const float* vs = v_hist + ((ull)pos * NKVH + kv) * HD;
        k1 = ks[i]; k2 = ks[i + 64];
        vd[i] = vs[i]; vd[i + 64] = vs[i + 64];
    } else {
        const int t = pos - HISTL;
        const float* ks = g_kn + (ull)t * (NKVH * HD) + kv * HD;
        const float* vs = g_vn + (ull)t * (NKVH * HD) + kv * HD;
        const float c = fcos[t * 64 + i];
        const float s = fsin[t * 64 + i];
        const float x1 = ks[i];
        const float x2 = ks[i + 64];
        k1 = x1 * c - x2 * s;
        k2 = x1 * s + x2 * c;
        vd[i] = vs[i]; vd[i + 64] = vs[i + 64];
    }
    __nv_bfloat16 h1, l1, h2, l2;
    split2(k1, h1, l1); split2(k2, h2, l2);
    const ull base = ((ull)(kv * KLEN + pos)) * HD;
    g_kh[base + i] = h1;       g_klo[base + i] = l1;
    g_kh[base + i + 64] = h2;  g_klo[base + i + 64] = l2;
}

// ---------------- transpose V -> V^T planes ----------------
__global__ void vt_kernel() {
    __shared__ float t[32][33];
    const int pos0 = blockIdx.x * 32, d0 = blockIdx.y * 32, kv = blockIdx.z;
    const int tx = threadIdx.x, ty = threadIdx.y;
    for (int r = ty; r < 32; r += 8)
        t[r][tx] = g_v[((ull)(kv * KLEN + pos0 + r)) * HD + d0 + tx];
    __syncthreads();
    for (int r = ty; r < 32; r += 8) {
        __nv_bfloat16 h, l;
        split2(t[tx][r], h, l);
        const ull o = ((ull)(kv * HD + d0 + r)) * KLEN + pos0 + tx;
        g_vth[o] = h; g_vtl[o] = l;
    }
}

// ================= HMMA flash attention: 128q x 64k, plane-split =================
// 8 warps: wm = wid>>1 (0..3, 32 q-rows each), wn = wid&1 (0..1).
// QK: wn splits 64 keys (32 each).  PV: wn splits 128 d-cols (64 each).
#define QSTR 272            // Q/K row stride (128 d x 2B + 16 pad)
#define VSTR 144            // V^T / P row stride (64 keys x 2B + 16 pad)
#define OFF_QH 0            // 128 x 272 = 34816
#define OFF_QL 34816
#define OFF_KH 69632        // 64 x 272 = 17408
#define OFF_KL 87040
#define OFF_V  104448       // 2 bufs x (Vh 18432 + Vl 18432)
#define VBUF_B 36864
#define OFF_PH 178176       // 128 x 144 = 18432
#define OFF_PL 196608
#define OFF_RS 215040       // 2 x 128 f32 = 1024
#define ATT_SMEM 216064

__global__ __launch_bounds__(256, 1) void attention_kernel()
{
    extern __shared__ __align__(1024) char asmem[];
    const uint32_t sb = smem_u32(asmem);
    const int h  = blockIdx.x;
    const int qb = 15 - blockIdx.y;      // heavy blocks first
    const int kvh = h / GRP;
    const int q0 = qb * 128;
    const int tid = threadIdx.x;
    const int lane = tid & 31;
    const int wid = tid >> 5;
    const int wm = wid >> 1;      // 0..3
    const int wn = wid & 1;       // 0..1
    const int n_tiles = 2 * qb + 34;

    const __nv_bfloat16* Qgh = g_qh  + ((ull)h * QL + q0) * HD;
    const __nv_bfloat16* Qgl = g_qlo + ((ull)h * QL + q0) * HD;
    const __nv_bfloat16* Kgh = g_kh  + ((ull)kvh * KLEN) * HD;
    const __nv_bfloat16* Kgl = g_klo + ((ull)kvh * KLEN) * HD;
    const __nv_bfloat16* Vgh = g_vth + ((ull)kvh * HD) * KLEN;
    const __nv_bfloat16* Vgl = g_vtl + ((ull)kvh * HD) * KLEN;

    // ---- prologue: Q planes (128 rows) + K[0] planes + V[0] planes ----
    for (int u = tid; u < 128 * 16; u += 256) {
        const int r = u >> 4, c = u & 15;
        cp_async16(sb + OFF_QH + r * QSTR + c * 16, Qgh + (ull)r * HD + c * 8);
        cp_async16(sb + OFF_QL + r * QSTR + c * 16, Qgl + (ull)r * HD + c * 8);
    }
    for (int u = tid; u < 64 * 16; u += 256) {
        const int r = u >> 4, c = u & 15;
        cp_async16(sb + OFF_KH + r * QSTR + c * 16, Kgh + (ull)r * HD + c * 8);
        cp_async16(sb + OFF_KL + r * QSTR + c * 16, Kgl + (ull)r * HD + c * 8);
    }
    for (int u = tid; u < 128 * 8; u += 256) {
        const int r = u >> 3, c = u & 7;
        cp_async16(sb + OFF_V + r * VSTR + c * 16,         Vgh + (ull)r * KLEN + c * 8);
        cp_async16(sb + OFF_V + 18432 + r * VSTR + c * 16, Vgl + (ull)r * KLEN + c * 8);
    }
    cp_commit();

    float accO[2][8][4];        // [mi][ni over 64 d-cols][4]
    float psum[2][2];
#pragma unroll
    for (int mi = 0; mi < 2; mi++) {
#pragma unroll
        for (int hf = 0; hf < 2; hf++) psum[mi][hf] = 0.f;
#pragma unroll
        for (int ni = 0; ni < 8; ni++)
#pragma unroll
            for (int r = 0; r < 4; r++) accO[mi][ni][r] = 0.f;
    }

    const int arow = wm * 32 + (lane & 15);            // q-row frag base (2 mi: +0, +16)
    const int acol = (lane & 16) ? 16 : 0;
    const int kbrow = wn * 32 + (lane & 7) + ((lane & 16) ? 8 : 0);   // key frag base
    const int kbcol = (lane & 8) ? 16 : 0;
    const int vbrow = wn * 64 + (lane & 7) + ((lane & 16) ? 8 : 0);   // d-row frag base (4 segs: +0,16,32,48)

    // ---- load Qh fragments ONCE for the whole block ----
    cp_wait0();
    __syncthreads();
    uint32_t qfh[8][2][4];
#pragma unroll
    for (int kk = 0; kk < 8; kk++) {
        ldsm4(qfh[kk][0], sb + OFF_QH + (uint32_t)(arow * QSTR + kk * 32 + acol));
        ldsm4(qfh[kk][1], sb + OFF_QH + (uint32_t)((arow + 16) * QSTR + kk * 32 + acol));
    }

    for (int kt = 0; kt < n_tiles; kt++) {
        cp_wait0();
        __syncthreads();           // tile data ready; prev PV done

        // ==== S = Q K^T (128q x 64k; this warp: 32q x 32k), 3 passes ====
        float S[2][4][4];
#pragma unroll
        for (int mi = 0; mi < 2; mi++)
#pragma unroll
            for (int nf = 0; nf < 4; nf++)
#pragma unroll
                for (int r = 0; r < 4; r++) S[mi][nf][r] = 0.f;

        // pass 1: Qh * Kh
#pragma unroll
        for (int kk = 0; kk < 8; kk++) {
            uint32_t k0[4], k1[4];
            ldsm4(k0, sb + OFF_KH + (uint32_t)(kbrow * QSTR + kk * 32 + kbcol));
            ldsm4(k1, sb + OFF_KH + (uint32_t)((kbrow + 16) * QSTR + kk * 32 + kbcol));
            mma16816(S[0][0], qfh[kk][0], &k0[0]);
            mma16816(S[0][1], qfh[kk][0], &k0[2]);
            mma16816(S[0][2], qfh[kk][0], &k1[0]);
            mma16816(S[0][3], qfh[kk][0], &k1[2]);
            mma16816(S[1][0], qfh[kk][1], &k0[0]);
            mma16816(S[1][1], qfh[kk][1], &k0[2]);
            mma16816(S[1][2], qfh[kk][1], &k1[0]);
            mma16816(S[1][3], qfh[kk][1], &k1[2]);
        }
        // pass 2: Qh * Kl
#pragma unroll
        for (int kk = 0; kk < 8; kk++) {
            uint32_t k0[4], k1[4];
            ldsm4(k0, sb + OFF_KL + (uint32_t)(kbrow * QSTR + kk * 32 + kbcol));
            ldsm4(k1, sb + OFF_KL + (uint32_t)((kbrow + 16) * QSTR + kk * 32 + kbcol));
            mma16816(S[0][0], qfh[kk][0], &k0[0]);
            mma16816(S[0][1], qfh[kk][0], &k0[2]);
            mma16816(S[0][2], qfh[kk][0], &k1[0]);
            mma16816(S[0][3], qfh[kk][0], &k1[2]);
            mma16816(S[1][0], qfh[kk][1], &k0[0]);
            mma16816(S[1][1], qfh[kk][1], &k0[2]);
            mma16816(S[1][2], qfh[kk][1], &k1[0]);
            mma16816(S[1][3], qfh[kk][1], &k1[2]);
        }
        // pass 3: Ql * Kh (both streamed)
#pragma unroll
        for (int kk = 0; kk < 8; kk++) {
            uint32_t t0[4], t1[4], k0[4], k1[4];
            ldsm4(t0, sb + OFF_QL + (uint32_t)(arow * QSTR + kk * 32 + acol));
            ldsm4(t1, sb + OFF_QL + (uint32_t)((arow + 16) * QSTR + kk * 32 + acol));
            ldsm4(k0, sb + OFF_KH + (uint32_t)(kbrow * QSTR + kk * 32 + kbcol));
            ldsm4(k1, sb + OFF_KH + (uint32_t)((kbrow + 16) * QSTR + kk * 32 + kbcol));
            mma16816(S[0][0], t0, &k0[0]);
            mma16816(S[0][1], t0, &k0[2]);
            mma16816(S[0][2], t0, &k1[0]);
            mma16816(S[0][3], t0, &k1[2]);
            mma16816(S[1][0], t1, &k0[0]);
            mma16816(S[1][1], t1, &k0[2]);
            mma16816(S[1][2], t1, &k1[0]);
            mma16816(S[1][3], t1, &k1[2]);
        }
        __syncthreads();           // all QK ldsm done -> K SMEM reusable

        // ---- prefetch next tile's K planes (+V alt buffer planes) ----
        if (kt + 1 < n_tiles) {
            const int kb2 = (kt + 1) * 64;
            for (int u = tid; u < 64 * 16; u += 256) {
                const int r = u >> 4, c = u & 15;
                cp_async16(sb + OFF_KH + r * QSTR + c * 16, Kgh + (ull)(kb2 + r) * HD + c * 8);
                cp_async16(sb + OFF_KL + r * QSTR + c * 16, Kgl + (ull)(kb2 + r) * HD + c * 8);
            }
            const uint32_t vbuf = sb + OFF_V + ((kt + 1) & 1) * VBUF_B;
            for (int u = tid; u < 128 * 8; u += 256) {
                const int r = u >> 3, c = u & 7;
                cp_async16(vbuf + r * VSTR + c * 16,         Vgh + (ull)r * KLEN + kb2 + c * 8);
                cp_async16(vbuf + 18432 + r * VSTR + c * 16, Vgl + (ull)r * KLEN + kb2 + c * 8);
            }
            cp_commit();
        }

        // ---- scale + mask + exp + write Ph/Pl planes + partial sums ----
        const int kb = kt * 64;
        const bool maskt = (kt >= 2 * qb + 32);
#pragma unroll
        for (int mi = 0; mi < 2; mi++)
#pragma unroll
            for (int nf = 0; nf < 4; nf++)
#pragma unroll
                for (int hf = 0; hf < 2; hf++) {
                    float s0 = S[mi][nf][hf * 2 + 0] * 0.08838834764831845f;
                    float s1 = S[mi][nf][hf * 2 + 1] * 0.08838834764831845f;
                    if (maskt) {
                        const int qg = q0 + wm * 32 + mi * 16 + (lane >> 2) + hf * 8;
                        const int kg = kb + wn * 32 + nf * 8 + (lane & 3) * 2;
                        if (kg > qg + HISTL)     s0 = -1e30f;
                        if (kg + 1 > qg + HISTL) s1 = -1e30f;
                    }
                    const float p0 = __expf(s0);
                    const float p1 = __expf(s1);
                    psum[mi][hf] += p0 + p1;
                    __nv_bfloat16 h0, l0, h1, l1;
                    split2(p0, h0, l0); split2(p1, h1, l1);
                    const int row = wm * 32 + mi * 16 + hf * 8 + (lane >> 2);
                    const int c2 = wn * 32 + nf * 8 + (lane & 3) * 2;
                    *(uint32_t*)(asmem + OFF_PH + row * VSTR + 2 * c2) = bfpack(h0, h1);
                    *(uint32_t*)(asmem + OFF_PL + row * VSTR + 2 * c2) = bfpack(l0, l1);
                }
        __syncthreads();           // P planes ready

        // ==== O += P @ V^T (this warp: 32q x 64d), 3 passes ====
        const uint32_t sPH = sb + OFF_PH;
        const uint32_t sPL = sb + OFF_PL;
        const uint32_t sVH = sb + OFF_V + (kt & 1) * VBUF_B;
        const uint32_t sVL = sVH + 18432;

        uint32_t pf[4][2][4];      // Ph fragments, held across passes 1-2
        // pass 1: Ph * Vh
#pragma unroll
        for (int kk = 0; kk < 4; kk++) {
            ldsm4(pf[kk][0], sPH + (uint32_t)(arow * VSTR + kk * 32 + acol));
            ldsm4(pf[kk][1], sPH + (uint32_t)((arow + 16) * VSTR + kk * 32 + acol));
#pragma unroll
            for (int seg = 0; seg < 2; seg++) {
                uint32_t v0[4], v1[4];
                ldsm4(v0, sVH + (uint32_t)((vbrow + seg * 32) * VSTR + kk * 32 + kbcol));
                ldsm4(v1, sVH + (uint32_t)((vbrow + seg * 32 + 16) * VSTR + kk * 32 + kbcol));
                mma16816(accO[0][seg * 4 + 0], pf[kk][0], &v0[0]);
                mma16816(accO[0][seg * 4 + 1], pf[kk][0], &v0[2]);
                mma16816(accO[0][seg * 4 + 2], pf[kk][0], &v1[0]);
                mma16816(accO[0][seg * 4 + 3], pf[kk][0], &v1[2]);
                mma16816(accO[1][seg * 4 + 0], pf[kk][1], &v0[0]);
                mma16816(accO[1][seg * 4 + 1], pf[kk][1], &v0[2]);
                mma16816(accO[1][seg * 4 + 2], pf[kk][1], &v1[0]);
                mma16816(accO[1][seg * 4 + 3], pf[kk][1], &v1[2]);
            }
        }
        // pass 2: Ph * Vl (Ph held)
#pragma unroll
        for (int kk = 0; kk < 4; kk++) {
#pragma unroll
            for (int seg = 0; seg < 2; seg++) {
                uint32_t v0[4], v1[4];
                ldsm4(v0, sVL + (uint32_t)((vbrow + seg * 32) * VSTR + kk * 32 + kbcol));
                ldsm4(v1, sVL + (uint32_t)((vbrow + seg * 32 + 16) * VSTR + kk * 32 + kbcol));
                mma16816(accO[0][seg * 4 + 0], pf[kk][0], &v0[0]);
                mma16816(accO[0][seg * 4 + 1], pf[kk][0], &v0[2]);
                mma16816(accO[0][seg * 4 + 2], pf[kk][0], &v1[0]);
                mma16816(accO[0][seg * 4 + 3], pf[kk][0], &v1[2]);
                mma16816(accO[1][seg * 4 + 0], pf[kk][1], &v0[0]);
                mma16816(accO[1][seg * 4 + 1], pf[kk][1], &v0[2]);
                mma16816(accO[1][seg * 4 + 2], pf[kk][1], &v1[0]);
                mma16816(accO[1][seg * 4 + 3], pf[kk][1], &v1[2]);
            }
        }
        // pass 3: Pl * Vh (both streamed)
#pragma unroll
        for (int kk = 0; kk < 4; kk++) {
            uint32_t p0[4], p1[4];
            ldsm4(p0, sPL + (uint32_t)(arow * VSTR + kk * 32 + acol));
            ldsm4(p1, sPL + (uint32_t)((arow + 16) * VSTR + kk * 32 + acol));
#pragma unroll
            for (int seg = 0; seg < 2; seg++) {
                uint32_t v0[4], v1[4];
                ldsm4(v0, sVH + (uint32_t)((vbrow + seg * 32) * VSTR + kk * 32 + kbcol));
                ldsm4(v1, sVH + (uint32_t)((vbrow + seg * 32 + 16) * VSTR + kk * 32 + kbcol));
                mma16816(accO[0][seg * 4 + 0], p0, &v0[0]);
                mma16816(accO[0][seg * 4 + 1], p0, &v0[2]);
                mma16816(accO[0][seg * 4 + 2], p0, &v1[0]);
                mma16816(accO[0][seg * 4 + 3], p0, &v1[2]);
                mma16816(accO[1][seg * 4 + 0], p1, &v0[0]);
                mma16816(accO[1][seg * 4 + 1], p1, &v0[2]);
                mma16816(accO[1][seg * 4 + 2], p1, &v1[0]);
                mma16816(accO[1][seg * 4 + 3], p1, &v1[2]);
            }
        }
    }

    // ---- one-time row-sum reduction (combine across the 2 n-warps) ----
    float* rs = (float*)(asmem + OFF_RS);
#pragma unroll
    for (int mi = 0; mi < 2; mi++)
#pragma unroll
        for (int hf = 0; hf < 2; hf++) {
            float v = psum[mi][hf];
            v += __shfl_xor_sync(0xffffffffu, v, 1);
            v += __shfl_xor_sync(0xffffffffu, v, 2);
            psum[mi][hf] = v;
        }
    __syncthreads();
    if ((lane & 3) == 0) {
#pragma unroll
        for (int mi = 0; mi < 2; mi++)
#pragma unroll
            for (int hf = 0; hf < 2; hf++)
                rs[wn * 128 + wm * 32 + mi * 16 + hf * 8 + (lane >> 2)] = psum[mi][hf];
    }
    __syncthreads();

    // ---- epilogue: normalize, write g_at3 triplets (A-side h,h,l) ----
#pragma unroll
    for (int mi = 0; mi < 2; mi++) {
#pragma unroll
        for (int hf = 0; hf < 2; hf++) {
            const int lrow = wm * 32 + mi * 16 + hf * 8 + (lane >> 2);
            const float lsum = rs[lrow] + rs[128 + lrow];
            const float inv = 1.f / lsum;
            const int row = q0 + lrow;
#pragma unroll
            for (int ni = 0; ni < 8; ni++) {
                const int dcol = wn * 64 + ni * 8 + (lane & 3) * 2;
                const float v0 = accO[mi][ni][hf * 2 + 0] * inv;
                const float v1 = accO[mi][ni][hf * 2 + 1] * inv;
                __nv_bfloat16 h0, l0, h1, l1;
                split2(v0, h0, l0); split2(v1, h1, l1);
                uint32_t* dp = (uint32_t*)(g_at3 + (ull)row * K3 + 3 * (h * HD + dcol));
                dp[0] = bfpack(h0, h0);
                dp[1] = bfpack(l0, h1);
                dp[2] = bfpack(h1, l1);
            }
        }
    }
}

// ---------------- launch ----------------
extern "C" void kernel_launch(void* const* d_in, const int* in_sizes, int n_in,
                              void* d_out, int out_size)
{
    const float* x     = (const float*)d_in[0];
    const float* Wq    = (const float*)d_in[1];
    const float* bq    = (const float*)d_in[2];
    const float* Wk    = (const float*)d_in[3];
    const float* bk    = (const float*)d_in[4];
    const float* Wv    = (const float*)d_in[5];
    const float* bv    = (const float*)d_in[6];
    const float* Wo    = (const float*)d_in[7];
    const float* khist = (const float*)d_in[8];
    const float* vhist = (const float*)d_in[9];
    const float* fcos  = (const float*)d_in[10];
    const float* fsin  = (const float*)d_in[11];
    float* out = (float*)d_out;

    cudaFuncSetAttribute(attention_kernel,
                         cudaFuncAttributeMaxDynamicSharedMemorySize, ATT_SMEM);
    cudaFuncSetAttribute(hmma_gemm_kernel,
                         cudaFuncAttributeMaxDynamicSharedMemorySize, GEMM_SMEM);

    conv_x3_kernel<<<QL * HID / 256, 256>>>(x);
    conv_wqkv3_kernel<<<dim3(64, 48), dim3(32, 8)>>>(Wq, Wk, Wv);
    conv_wo3_kernel<<<dim3(48, 48), dim3(32, 8)>>>(Wo);

    hmma_gemm_kernel<<<dim3(16, 16), 256, GEMM_SMEM>>>(0, nullptr, bq, bk, bv);

    rope_q_kernel<<<QL, NH * 64>>>(fcos, fsin);
    build_kv_kernel<<<dim3(KLEN, NKVH), 64>>>(khist, vhist, fcos, fsin);
    vt_kernel<<<dim3(KLEN / 32, HD / 32, NKVH), dim3(32, 8)>>>();

    attention_kernel<<<dim3(NH, 16), 256, ATT_SMEM>>>();

    hmma_gemm_kernel<<<dim3(12, 16), 256, GEMM_SMEM>>>(1, out, nullptr, nullptr, nullptr);
}

// round 14
// speedup vs baseline: 1.0140x; 1.0140x over previous
#include <cuda_runtime.h>
#include <cuda_bf16.h>
#include <cstdint>

typedef unsigned long long ull;

#define QL    2048
#define HISTL 2048
#define KLEN  4096
#define NH    12
#define NKVH  2
#define HD    128
#define HID   1536
#define GRP   6
#define K3    4608           // 3 * 1536 (hi/lo compensated K extension, GEMM)

// ---------------- scratch (static device globals; no allocation) ----------------
__device__ float g_q[QL * HID];          // Q projection (pre-RoPE, f32)
__device__ float g_kn[QL * NKVH * HD];   // new K projection (pre-RoPE)
__device__ float g_vn[QL * NKVH * HD];   // new V projection
__device__ float g_v[NKVH * KLEN * HD];  // full V (f32, for transpose)

// GEMM triplet operands (proven R7-R9 path)
__device__ __nv_bfloat16 g_x3[QL * K3];
__device__ __nv_bfloat16 g_w3[2048 * K3];
__device__ __nv_bfloat16 g_wo3[HID * K3];
__device__ __nv_bfloat16 g_at3[QL * K3];

// attention plane-split operands (hi / lo separate)
__device__ __nv_bfloat16 g_qh[NH * QL * HD];
__device__ __nv_bfloat16 g_qlo[NH * QL * HD];
__device__ __nv_bfloat16 g_kh[NKVH * KLEN * HD];
__device__ __nv_bfloat16 g_klo[NKVH * KLEN * HD];
__device__ __nv_bfloat16 g_vth[NKVH * HD * KLEN];   // V^T hi: [kv][d][pos]
__device__ __nv_bfloat16 g_vtl[NKVH * HD * KLEN];   // V^T lo

// ---------------- helpers ----------------
__device__ __forceinline__ uint32_t smem_u32(const void* p) {
    uint32_t a;
    asm("{ .reg .u64 t; cvta.to.shared.u64 t, %1; cvt.u32.u64 %0, t; }" : "=r"(a) : "l"(p));
    return a;
}
#define SWZ128(off) ((off) ^ (((off) >> 3) & 0x70))

__device__ __forceinline__ void ldsm4(uint32_t* r, uint32_t addr) {
    asm volatile("ldmatrix.sync.aligned.m8n8.x4.shared.b16 {%0,%1,%2,%3}, [%4];"
        : "=r"(r[0]), "=r"(r[1]), "=r"(r[2]), "=r"(r[3]) : "r"(addr));
}
__device__ __forceinline__ void mma16816(float* d, const uint32_t* a, const uint32_t* b) {
    asm volatile("mma.sync.aligned.m16n8k16.row.col.f32.bf16.bf16.f32 "
        "{%0,%1,%2,%3},{%4,%5,%6,%7},{%8,%9},{%0,%1,%2,%3};"
        : "+f"(d[0]), "+f"(d[1]), "+f"(d[2]), "+f"(d[3])
        : "r"(a[0]), "r"(a[1]), "r"(a[2]), "r"(a[3]), "r"(b[0]), "r"(b[1]));
}
__device__ __forceinline__ void cp_async16(uint32_t saddr, const void* gptr) {
    asm volatile("cp.async.cg.shared.global [%0], [%1], 16;"
        :: "r"(saddr), "l"((size_t)__cvta_generic_to_global(gptr)) : "memory");
}
__device__ __forceinline__ void cp_commit() { asm volatile("cp.async.commit_group;" ::: "memory"); }
__device__ __forceinline__ void cp_wait0()  { asm volatile("cp.async.wait_group 0;" ::: "memory"); }
__device__ __forceinline__ void cp_wait1()  { asm volatile("cp.async.wait_group 1;" ::: "memory"); }

__device__ __forceinline__ void split2(float v, __nv_bfloat16& h, __nv_bfloat16& l) {
    h = __float2bfloat16(v);
    l = __float2bfloat16(v - __bfloat162float(h));
}
__device__ __forceinline__ uint32_t bfpack(__nv_bfloat16 a, __nv_bfloat16 b) {
    return (uint32_t)__bfloat16_as_ushort(a) | ((uint32_t)__bfloat16_as_ushort(b) << 16);
}

// ================= conversion kernels =================
__global__ void conv_x3_kernel(const float* __restrict__ src) {
    const int i = blockIdx.x * blockDim.x + threadIdx.x;
    const int m = i / HID, k = i % HID;
    __nv_bfloat16 h, l;
    split2(src[i], h, l);
    __nv_bfloat16* p = g_x3 + (ull)m * K3 + 3 * k;
    p[0] = h; p[1] = h; p[2] = l;
}

__global__ void conv_wqkv3_kernel(const float* __restrict__ Wq,
                                  const float* __restrict__ Wk,
                                  const float* __restrict__ Wv) {
    __shared__ float t[32][33];
    const int n0 = blockIdx.x * 32, k0 = blockIdx.y * 32;
    const int tx = threadIdx.x, ty = threadIdx.y;
    const float* W; int nb, ld;
    if (n0 < 1536)      { W = Wq; nb = n0;        ld = HID; }
    else if (n0 < 1792) { W = Wk; nb = n0 - 1536; ld = NKVH * HD; }
    else                { W = Wv; nb = n0 - 1792; ld = NKVH * HD; }
    for (int r = ty; r < 32; r += 8)
        t[r][tx] = W[(ull)(k0 + r) * ld + nb + tx];
    __syncthreads();
    for (int r = ty; r < 32; r += 8) {
        __nv_bfloat16 h, l;
        split2(t[tx][r], h, l);
        __nv_bfloat16* p = g_w3 + (ull)(n0 + r) * K3 + 3 * (k0 + tx);
        p[0] = h; p[1] = l; p[2] = h;
    }
}

__global__ void conv_wo3_kernel(const float* __restrict__ Wo) {
    __shared__ float t[32][33];
    const int n0 = blockIdx.x * 32, k0 = blockIdx.y * 32;
    const int tx = threadIdx.x, ty = threadIdx.y;
    for (int r = ty; r < 32; r += 8)
        t[r][tx] = Wo[(ull)(k0 + r) * HID + n0 + tx];
    __syncthreads();
    for (int r = ty; r < 32; r += 8) {
        __nv_bfloat16 h, l;
        split2(t[tx][r], h, l);
        __nv_bfloat16* p = g_wo3 + (ull)(n0 + r) * K3 + 3 * (k0 + tx);
        p[0] = h; p[1] = l; p[2] = h;
    }
}

// ================= HMMA GEMM: CTA tile 128x256, warp tile 64x64 =================
#define CHK     64
#define NCHUNK  (K3 / CHK)          // 72
#define A_TB    16384               // 128 rows x 128B
#define B_TB    32768               // 256 rows x 128B
#define BUF_TB  (A_TB + B_TB)       // 49152
#define NBUF    3
#define GEMM_SMEM (NBUF * BUF_TB)   // 147456

__global__ __launch_bounds__(256, 1) void hmma_gemm_kernel(
    int mode, float* __restrict__ outp,
    const float* __restrict__ bq, const float* __restrict__ bk, const float* __restrict__ bv)
{
    extern __shared__ __align__(1024) char dynsm[];
    const uint32_t sbase = smem_u32(dynsm);
    const int tid  = threadIdx.x;
    const int lane = tid & 31;
    const int wid  = tid >> 5;
    const int wm   = wid >> 2;          // 0..1  (64 rows each)
    const int wn   = wid & 3;           // 0..3  (64 cols each)
    const int m0   = blockIdx.y * 128;
    const int n0   = blockIdx.x * 256;

    const __nv_bfloat16* __restrict__ A3 = (mode == 0) ? g_x3 : g_at3;
    const __nv_bfloat16* __restrict__ B3 = (mode == 0) ? g_w3 : g_wo3;

    float d[4][8][4];
#pragma unroll
    for (int mi = 0; mi < 4; mi++)
#pragma unroll
        for (int ni = 0; ni < 8; ni++)
#pragma unroll
            for (int r = 0; r < 4; r++) d[mi][ni][r] = 0.f;

    const int lr = tid >> 3;            // 0..31
    const int lg = tid & 7;

    // prologue: chunks 0,1 -> bufs 0,1
#pragma unroll
    for (int pc = 0; pc < 2; pc++) {
        const uint32_t sA = sbase + pc * BUF_TB, sB = sA + A_TB;
        const int k0 = pc * CHK;
#pragma unroll
        for (int it = 0; it < 4; it++) {
            const int r = lr + it * 32;
            const uint32_t so = SWZ128((uint32_t)(r * 128 + lg * 16));
            cp_async16(sA + so, A3 + (ull)(m0 + r) * K3 + k0 + lg * 8);
        }
#pragma unroll
        for (int it = 0; it < 8; it++) {
            const int r = lr + it * 32;
            const uint32_t so = SWZ128((uint32_t)(r * 128 + lg * 16));
            cp_async16(sB + so, B3 + (ull)(n0 + r) * K3 + k0 + lg * 8);
        }
        cp_commit();
    }

    const int arow = wm * 64 + (lane & 15);
    const int acol = (lane & 16) ? 16 : 0;
    const int brow = wn * 64 + (lane & 7) + ((lane & 16) ? 8 : 0);
    const int bcol = (lane & 8) ? 16 : 0;

    int ldbuf = 2;
    for (int c = 0; c < NCHUNK; c++) {
        cp_wait1();
        __syncthreads();
        if (c + 2 < NCHUNK) {
            const uint32_t sA = sbase + (uint32_t)ldbuf * BUF_TB, sB = sA + A_TB;
            const int k0 = (c + 2) * CHK;
#pragma unroll
            for (int it = 0; it < 4; it++) {
                const int r = lr + it * 32;
                const uint32_t so = SWZ128((uint32_t)(r * 128 + lg * 16));
                cp_async16(sA + so, A3 + (ull)(m0 + r) * K3 + k0 + lg * 8);
            }
#pragma unroll
            for (int it = 0; it < 8; it++) {
                const int r = lr + it * 32;
                const uint32_t so = SWZ128((uint32_t)(r * 128 + lg * 16));
                cp_async16(sB + so, B3 + (ull)(n0 + r) * K3 + k0 + lg * 8);
            }
            cp_commit();
            if (++ldbuf == NBUF) ldbuf = 0;
        }
        const uint32_t cb = (uint32_t)(c % NBUF) * BUF_TB;
        const uint32_t sA = sbase + cb, sB = sbase + cb + A_TB;
#pragma unroll
        for (int kk = 0; kk < 4; kk++) {
            uint32_t a[4][4], bb[8][2];
#pragma unroll
            for (int mi = 0; mi < 4; mi++)
                ldsm4(a[mi], sA + SWZ128((uint32_t)((arow + mi * 16) * 128 + kk * 32 + acol)));
#pragma unroll
            for (int nj = 0; nj < 4; nj++) {
                uint32_t t4[4];
                ldsm4(t4, sB + SWZ128((uint32_t)((brow + nj * 16) * 128 + kk * 32 + bcol)));
                bb[nj * 2][0] = t4[0]; bb[nj * 2][1] = t4[1];
                bb[nj * 2 + 1][0] = t4[2]; bb[nj * 2 + 1][1] = t4[3];
            }
#pragma unroll
            for (int mi = 0; mi < 4; mi++)
#pragma unroll
                for (int ni = 0; ni < 8; ni++)
                    mma16816(d[mi][ni], a[mi], bb[ni]);
        }
        __syncthreads();
    }

    // epilogue routing
    float* dst; int ldc; const float* bias; int coff;
    if (mode == 1)             { dst = outp; ldc = HID;       bias = nullptr; coff = n0; }
    else if (blockIdx.x < 6)   { dst = g_q;  ldc = HID;       bias = bq + n0; coff = n0; }
    else if (blockIdx.x == 6)  { dst = g_kn; ldc = NKVH * HD; bias = bk;      coff = 0; }
    else                       { dst = g_vn; ldc = NKVH * HD; bias = bv;      coff = 0; }

#pragma unroll
    for (int mi = 0; mi < 4; mi++) {
        const int r0 = m0 + wm * 64 + mi * 16 + (lane >> 2);
#pragma unroll
        for (int ni = 0; ni < 8; ni++) {
            const int cl = wn * 64 + ni * 8 + (lane & 3) * 2;
            float b0 = 0.f, b1 = 0.f;
            if (bias) { b0 = bias[cl]; b1 = bias[cl + 1]; }
            float2 v0 = { d[mi][ni][0] + b0, d[mi][ni][1] + b1 };
            float2 v1 = { d[mi][ni][2] + b0, d[mi][ni][3] + b1 };
            *(float2*)(dst + (ull)r0 * ldc + coff + cl)       = v0;
            *(float2*)(dst + (ull)(r0 + 8) * ldc + coff + cl) = v1;
        }
    }
}

// ---------------- RoPE on Q -> Qh/Ql planes ----------------
__global__ void rope_q_kernel(const float* __restrict__ fcos, const float* __restrict__ fsin)
{
    const int t = blockIdx.x;
    const int h = threadIdx.x >> 6;
    const int i = threadIdx.x & 63;
    const float* q = g_q + (ull)t * HID + h * HD;
    const float c = fcos[t * 64 + i];
    const float s = fsin[t * 64 + i];
    const float x1 = q[i];
    const float x2 = q[i + 64];
    const float r1 = x1 * c - x2 * s;
    const float r2 = x1 * s + x2 * c;
    __nv_bfloat16 h1, l1, h2, l2;
    split2(r1, h1, l1); split2(r2, h2, l2);
    const ull base = ((ull)h * QL + t) * HD;
    g_qh[base + i] = h1;       g_qlo[base + i] = l1;
    g_qh[base + i + 64] = h2;  g_qlo[base + i + 64] = l2;
}

// ---------------- build full K planes + V (f32) ----------------
__global__ void build_kv_kernel(
    const float* __restrict__ k_hist, const float* __restrict__ v_hist,
    const float* __restrict__ fcos, const float* __restrict__ fsin)
{
    const int pos = blockIdx.x;
    const int kv = blockIdx.y;
    const int i = threadIdx.x;
    float* vd = g_v + ((ull)(kv * KLEN + pos)) * HD;
    float k1, k2;
    if (pos < HISTL) {
        const float* ks = k_hist + ((ull)pos * NKVH + kv) * HD;
        const float* vs = v_hist + ((ull)pos * NKVH + kv) * HD;
        k1 = ks[i]; k2 = ks[i + 64];
        vd[i] = vs[i]; vd[i + 64] = vs[i + 64];
    } else {
        const int t = pos - HISTL;
        const float* ks = g_kn + (ull)t * (NKVH * HD) + kv * HD;
        const float* vs = g_vn + (ull)t * (NKVH * HD) + kv * HD;
        const float c = fcos[t * 64 + i];
        const float s = fsin[t * 64 + i];
        const float x1 = ks[i];
        const float x2 = ks[i + 64];
        k1 = x1 * c - x2 * s;
        k2 = x1 * s + x2 * c;
        vd[i] = vs[i]; vd[i + 64] = vs[i + 64];
    }
    __nv_bfloat16 h1, l1, h2, l2;
    split2(k1, h1, l1); split2(k2, h2, l2);
    const ull base = ((ull)(kv * KLEN + pos)) * HD;
    g_kh[base + i] = h1;       g_klo[base + i] = l1;
    g_kh[base + i + 64] = h2;  g_klo[base + i + 64] = l2;
}

// ---------------- transpose V -> V^T planes ----------------
__global__ void vt_kernel() {
    __shared__ float t[32][33];
    const int pos0 = blockIdx.x * 32, d0 = blockIdx.y * 32, kv = blockIdx.z;
    const int tx = threadIdx.x, ty = threadIdx.y;
    for (int r = ty; r < 32; r += 8)
        t[r][tx] = g_v[((ull)(kv * KLEN + pos0 + r)) * HD + d0 + tx];
    __syncthreads();
    for (int r = ty; r < 32; r += 8) {
        __nv_bfloat16 h, l;
        split2(t[tx][r], h, l);
        const ull o = ((ull)(kv * HD + d0 + r)) * KLEN + pos0 + tx;
        g_vth[o] = h; g_vtl[o] = l;
    }
}

// ================= HMMA flash attention (R11 proven: 64q x 64k, Q block-held) =================
#define QSTR 272            // Qh/Ql/Kh/Kl row stride (128 d x 2B + 16 pad)
#define VSTR 144            // Vh/Vl/Ph/Pl row stride (64 keys x 2B + 16 pad)
#define OFF_QH 0
#define OFF_QL 17408
#define OFF_KH 34816
#define OFF_KL 52224
#define OFF_V  69632        // per buf: Vh (18432) then Vl (18432); 2 bufs
#define VBUF_B 36864
#define OFF_PH 143360
#define OFF_PL 152576
#define OFF_RS 161792
#define ATT_SMEM 162816

__global__ __launch_bounds__(256, 1) void attention_kernel()
{
    extern __shared__ __align__(1024) char asmem[];
    const uint32_t sb = smem_u32(asmem);
    const int h  = blockIdx.x;
    const int qb = 31 - blockIdx.y;
    const int kvh = h / GRP;
    const int q0 = qb * 64;
    const int tid = threadIdx.x;
    const int lane = tid & 31;
    const int wid = tid >> 5;
    const int wm = wid >> 2;      // 0..1
    const int wn = wid & 3;       // 0..3
    const int n_tiles = qb + 33;

    const __nv_bfloat16* Qgh = g_qh  + ((ull)h * QL + q0) * HD;
    const __nv_bfloat16* Qgl = g_qlo + ((ull)h * QL + q0) * HD;
    const __nv_bfloat16* Kgh = g_kh  + ((ull)kvh * KLEN) * HD;
    const __nv_bfloat16* Kgl = g_klo + ((ull)kvh * KLEN) * HD;
    const __nv_bfloat16* Vgh = g_vth + ((ull)kvh * HD) * KLEN;
    const __nv_bfloat16* Vgl = g_vtl + ((ull)kvh * HD) * KLEN;

    // ---- prologue: Q planes + K[0] planes + V[0] planes ----
    for (int u = tid; u < 64 * 16; u += 256) {
        const int r = u >> 4, c = u & 15;
        cp_async16(sb + OFF_QH + r * QSTR + c * 16, Qgh + (ull)r * HD + c * 8);
        cp_async16(sb + OFF_QL + r * QSTR + c * 16, Qgl + (ull)r * HD + c * 8);
        cp_async16(sb + OFF_KH + r * QSTR + c * 16, Kgh + (ull)r * HD + c * 8);
        cp_async16(sb + OFF_KL + r * QSTR + c * 16, Kgl + (ull)r * HD + c * 8);
    }
    for (int u = tid; u < 128 * 8; u += 256) {
        const int r = u >> 3, c = u & 7;
        cp_async16(sb + OFF_V + r * VSTR + c * 16,         Vgh + (ull)r * KLEN + c * 8);
        cp_async16(sb + OFF_V + 18432 + r * VSTR + c * 16, Vgl + (ull)r * KLEN + c * 8);
    }
    cp_commit();

    float accO[2][4][4];
    float psum[2][2];
#pragma unroll
    for (int mi = 0; mi < 2; mi++) {
#pragma unroll
        for (int hf = 0; hf < 2; hf++) psum[mi][hf] = 0.f;
#pragma unroll
        for (int ni = 0; ni < 4; ni++)
#pragma unroll
            for (int r = 0; r < 4; r++) accO[mi][ni][r] = 0.f;
    }

    const int arow = wm * 32 + (lane & 15);
    const int acol = (lane & 16) ? 16 : 0;
    const int qbrow = wn * 16 + (lane & 7) + ((lane & 16) ? 8 : 0);
    const int vbrow = wn * 32 + (lane & 7) + ((lane & 16) ? 8 : 0);
    const int kbcol = (lane & 8) ? 16 : 0;

    // ---- load Qh fragments ONCE for the whole block (held in registers) ----
    cp_wait0();
    __syncthreads();
    uint32_t qfh[8][2][4];
#pragma unroll
    for (int kk = 0; kk < 8; kk++) {
        ldsm4(qfh[kk][0], sb + OFF_QH + (uint32_t)(arow * QSTR + kk * 32 + acol));
        ldsm4(qfh[kk][1], sb + OFF_QH + (uint32_t)((arow + 16) * QSTR + kk * 32 + acol));
    }

    for (int kt = 0; kt < n_tiles; kt++) {
        cp_wait0();
        __syncthreads();           // tile data ready; prev PV done

        // ==== S = Q K^T, 3 passes (Qh held in qfh across all tiles) ====
        float S[2][2][4];
#pragma unroll
        for (int mi = 0; mi < 2; mi++)
#pragma unroll
            for (int nf = 0; nf < 2; nf++)
#pragma unroll
                for (int r = 0; r < 4; r++) S[mi][nf][r] = 0.f;

        uint32_t kf[8][4];         // Kh fragments, held within tile
        // pass 1: Qh * Kh  (K load + hold)
#pragma unroll
        for (int kk = 0; kk < 8; kk++) {
            ldsm4(kf[kk], sb + OFF_KH + (uint32_t)(qbrow * QSTR + kk * 32 + kbcol));
            mma16816(S[0][0], qfh[kk][0], &kf[kk][0]);
            mma16816(S[0][1], qfh[kk][0], &kf[kk][2]);
            mma16816(S[1][0], qfh[kk][1], &kf[kk][0]);
            mma16816(S[1][1], qfh[kk][1], &kf[kk][2]);
        }
        // pass 2: Qh * Kl  (Kl streamed)
#pragma unroll
        for (int kk = 0; kk < 8; kk++) {
            uint32_t t4[4];
            ldsm4(t4, sb + OFF_KL + (uint32_t)(qbrow * QSTR + kk * 32 + kbcol));
            mma16816(S[0][0], qfh[kk][0], &t4[0]);
            mma16816(S[0][1], qfh[kk][0], &t4[2]);
            mma16816(S[1][0], qfh[kk][1], &t4[0]);
            mma16816(S[1][1], qfh[kk][1], &t4[2]);
        }
        // pass 3: Ql * Kh  (Ql streamed, Kh held)
#pragma unroll
        for (int kk = 0; kk < 8; kk++) {
            uint32_t t0[4], t1[4];
            ldsm4(t0, sb + OFF_QL + (uint32_t)(arow * QSTR + kk * 32 + acol));
            ldsm4(t1, sb + OFF_QL + (uint32_t)((arow + 16) * QSTR + kk * 32 + acol));
            mma16816(S[0][0], t0, &kf[kk][0]);
            mma16816(S[0][1], t0, &kf[kk][2]);
            mma16816(S[1][0], t1, &kf[kk][0]);
            mma16816(S[1][1], t1, &kf[kk][2]);
        }
        __syncthreads();           // all QK ldsm done -> K SMEM reusable

        // ---- prefetch next tile's K planes (+V alt buffer planes) ----
        if (kt + 1 < n_tiles) {
            const int kb2 = (kt + 1) * 64;
            for (int u = tid; u < 64 * 16; u += 256) {
                const int r = u >> 4, c = u & 15;
                cp_async16(sb + OFF_KH + r * QSTR + c * 16, Kgh + (ull)(kb2 + r) * HD + c * 8);
                cp_async16(sb + OFF_KL + r * QSTR + c * 16, Kgl + (ull)(kb2 + r) * HD + c * 8);
            }
            const uint32_t vbuf = sb + OFF_V + ((kt + 1) & 1) * VBUF_B;
            for (int u = tid; u < 128 * 8; u += 256) {
                const int r = u >> 3, c = u & 7;
                cp_async16(vbuf + r * VSTR + c * 16,         Vgh + (ull)r * KLEN + kb2 + c * 8);
                cp_async16(vbuf + 18432 + r * VSTR + c * 16, Vgl + (ull)r * KLEN + kb2 + c * 8);
            }
            cp_commit();
        }

        // ---- scale + mask + exp + write Ph/Pl planes + partial sums ----
        const int kb = kt * 64;
        const bool maskt = (kt == qb + 32);
#pragma unroll
        for (int mi = 0; mi < 2; mi++)
#pragma unroll
            for (int nf = 0; nf < 2; nf++)
#pragma unroll
                for (int hf = 0; hf < 2; hf++) {
                    float s0 = S[mi][nf][hf * 2 + 0] * 0.08838834764831845f;
                    float s1 = S[mi][nf][hf * 2 + 1] * 0.08838834764831845f;
                    if (maskt) {
                        const int qg = q0 + wm * 32 + mi * 16 + (lane >> 2) + hf * 8;
                        const int kg = kb + wn * 16 + nf * 8 + (lane & 3) * 2;
                        if (kg > qg + HISTL)     s0 = -1e30f;
                        if (kg + 1 > qg + HISTL) s1 = -1e30f;
                    }
                    const float p0 = __expf(s0);
                    const float p1 = __expf(s1);
                    psum[mi][hf] += p0 + p1;
                    __nv_bfloat16 h0, l0, h1, l1;
                    split2(p0, h0, l0); split2(p1, h1, l1);
                    const int row = wm * 32 + mi * 16 + hf * 8 + (lane >> 2);
                    const int c2 = wn * 16 + nf * 8 + (lane & 3) * 2;
                    *(uint32_t*)(asmem + OFF_PH + row * VSTR + 2 * c2) = bfpack(h0, h1);
                    *(uint32_t*)(asmem + OFF_PL + row * VSTR + 2 * c2) = bfpack(l0, l1);
                }
        __syncthreads();           // P planes ready

        // ==== O += P @ V^T, 3 passes with held fragments ====
        const uint32_t sPH = sb + OFF_PH;
        const uint32_t sPL = sb + OFF_PL;
        const uint32_t sVH = sb + OFF_V + (kt & 1) * VBUF_B;
        const uint32_t sVL = sVH + 18432;

        uint32_t pf[4][2][4];      // Ph fragments, held
        uint32_t vf[4][2][4];      // Vh fragments, held
        // pass 1: Ph * Vh
#pragma unroll
        for (int kk = 0; kk < 4; kk++) {
            ldsm4(pf[kk][0], sPH + (uint32_t)(arow * VSTR + kk * 32 + acol));
            ldsm4(pf[kk][1], sPH + (uint32_t)((arow + 16) * VSTR + kk * 32 + acol));
            ldsm4(vf[kk][0], sVH + (uint32_t)(vbrow * VSTR + kk * 32 + kbcol));
            ldsm4(vf[kk][1], sVH + (uint32_t)((vbrow + 16) * VSTR + kk * 32 + kbcol));
            mma16816(accO[0][0], pf[kk][0], &vf[kk][0][0]);
            mma16816(accO[0][1], pf[kk][0], &vf[kk][0][2]);
            mma16816(accO[0][2], pf[kk][0], &vf[kk][1][0]);
            mma16816(accO[0][3], pf[kk][0], &vf[kk][1][2]);
            mma16816(accO[1][0], pf[kk][1], &vf[kk][0][0]);
            mma16816(accO[1][1], pf[kk][1], &vf[kk][0][2]);
            mma16816(accO[1][2], pf[kk][1], &vf[kk][1][0]);
            mma16816(accO[1][3], pf[kk][1], &vf[kk][1][2]);
        }
        // pass 2: Ph * Vl  (Ph held, Vl streamed)
#pragma unroll
        for (int kk = 0; kk < 4; kk++) {
            uint32_t t0[4], t1[4];
            ldsm4(t0, sVL + (uint32_t)(vbrow * VSTR + kk * 32 + kbcol));
            ldsm4(t1, sVL + (uint32_t)((vbrow + 16) * VSTR + kk * 32 + kbcol));
            mma16816(accO[0][0], pf[kk][0], &t0[0]);
            mma16816(accO[0][1], pf[kk][0], &t0[2]);
            mma16816(accO[0][2], pf[kk][0], &t1[0]);
            mma16816(accO[0][3], pf[kk][0], &t1[2]);
            mma16816(accO[1][0], pf[kk][1], &t0[0]);
            mma16816(accO[1][1], pf[kk][1], &t0[2]);
            mma16816(accO[1][2], pf[kk][1], &t1[0]);
            mma16816(accO[1][3], pf[kk][1], &t1[2]);
        }
        // pass 3: Pl * Vh  (Pl streamed, Vh held)
#pragma unroll
        for (int kk = 0; kk < 4; kk++) {
            uint32_t p0[4], p1[4];
            ldsm4(p0, sPL + (uint32_t)(arow * VSTR + kk * 32 + acol));
            ldsm4(p1, sPL + (uint32_t)((arow + 16) * VSTR + kk * 32 + acol));
            mma16816(accO[0][0], p0, &vf[kk][0][0]);
            mma16816(accO[0][1], p0, &vf[kk][0][2]);
            mma16816(accO[0][2], p0, &vf[kk][1][0]);
            mma16816(accO[0][3], p0, &vf[kk][1][2]);
            mma16816(accO[1][0], p1, &vf[kk][0][0]);
            mma16816(accO[1][1], p1, &vf[kk][0][2]);
            mma16816(accO[1][2], p1, &vf[kk][1][0]);
            mma16816(accO[1][3], p1, &vf[kk][1][2]);
        }
    }

    // ---- one-time row-sum reduction ----
    float* rs = (float*)(asmem + OFF_RS);
#pragma unroll
    for (int mi = 0; mi < 2; mi++)
#pragma unroll
        for (int hf = 0; hf < 2; hf++) {
            float v = psum[mi][hf];
            v += __shfl_xor_sync(0xffffffffu, v, 1);
            v += __shfl_xor_sync(0xffffffffu, v, 2);
            psum[mi][hf] = v;
        }
    __syncthreads();
    if ((lane & 3) == 0) {
#pragma unroll
        for (int mi = 0; mi < 2; mi++)
#pragma unroll
            for (int hf = 0; hf < 2; hf++)
                rs[wn * 64 + wm * 32 + mi * 16 + hf * 8 + (lane >> 2)] = psum[mi][hf];
    }
    __syncthreads();

    // ---- epilogue: normalize, write g_at3 triplets (A-side h,h,l) ----
#pragma unroll
    for (int mi = 0; mi < 2; mi++) {
#pragma unroll
        for (int hf = 0; hf < 2; hf++) {
            const int lrow = wm * 32 + mi * 16 + hf * 8 + (lane >> 2);
            const float lsum = rs[0 * 64 + lrow] + rs[1 * 64 + lrow]
                             + rs[2 * 64 + lrow] + rs[3 * 64 + lrow];
            const float inv = 1.f / lsum;
            const int row = q0 + lrow;
#pragma unroll
            for (int ni = 0; ni < 4; ni++) {
                const int dcol = wn * 32 + ni * 8 + (lane & 3) * 2;
                const float v0 = accO[mi][ni][hf * 2 + 0] * inv;
                const float v1 = accO[mi][ni][hf * 2 + 1] * inv;
                __nv_bfloat16 h0, l0, h1, l1;
                split2(v0, h0, l0); split2(v1, h1, l1);
                uint32_t* dp = (uint32_t*)(g_at3 + (ull)row * K3 + 3 * (h * HD + dcol));
                dp[0] = bfpack(h0, h0);
                dp[1] = bfpack(l0, h1);
                dp[2] = bfpack(h1, l1);
            }
        }
    }
}

// ---------------- launch ----------------
extern "C" void kernel_launch(void* const* d_in, const int* in_sizes, int n_in,
                              void* d_out, int out_size)
{
    const float* x     = (const float*)d_in[0];
    const float* Wq    = (const float*)d_in[1];
    const float* bq    = (const float*)d_in[2];
    const float* Wk    = (const float*)d_in[3];
    const float* bk    = (const float*)d_in[4];
    const float* Wv    = (const float*)d_in[5];
    const float* bv    = (const float*)d_in[6];
    const float* Wo    = (const float*)d_in[7];
    const float* khist = (const float*)d_in[8];
    const float* vhist = (const float*)d_in[9];
    const float* fcos  = (const float*)d_in[10];
    const float* fsin  = (const float*)d_in[11];
    float* out = (float*)d_out;

    cudaFuncSetAttribute(attention_kernel,
                         cudaFuncAttributeMaxDynamicSharedMemorySize, ATT_SMEM);
    cudaFuncSetAttribute(hmma_gemm_kernel,
                         cudaFuncAttributeMaxDynamicSharedMemorySize, GEMM_SMEM);

    conv_x3_kernel<<<QL * HID / 256, 256>>>(x);
    conv_wqkv3_kernel<<<dim3(64, 48), dim3(32, 8)>>>(Wq, Wk, Wv);
    conv_wo3_kernel<<<dim3(48, 48), dim3(32, 8)>>>(Wo);

    // QKV projection: N=2048 in 256-col tiles -> grid (8, 16)
    hmma_gemm_kernel<<<dim3(8, 16), 256, GEMM_SMEM>>>(0, nullptr, bq, bk, bv);

    rope_q_kernel<<<QL, NH * 64>>>(fcos, fsin);
    build_kv_kernel<<<dim3(KLEN, NKVH), 64>>>(khist, vhist, fcos, fsin);
    vt_kernel<<<dim3(KLEN / 32, HD / 32, NKVH), dim3(32, 8)>>>();

    attention_kernel<<<dim3(NH, 32), 256, ATT_SMEM>>>();

    // O projection: N=1536 in 256-col tiles -> grid (6, 16)
    hmma_gemm_kernel<<<dim3(6, 16), 256, GEMM_SMEM>>>(1, out, nullptr, nullptr, nullptr);
}

// round 15
// speedup vs baseline: 1.3683x; 1.3495x over previous
#include <cuda_runtime.h>
#include <cuda_bf16.h>
#include <cuda_fp16.h>
#include <cstdint>

typedef unsigned long long ull;

#define QL    2048
#define HISTL 2048
#define KLEN  4096
#define NH    12
#define NKVH  2
#define HD    128
#define HID   1536
#define GRP   6
#define K3    4608           // 3 * 1536 (hi/lo compensated K extension, GEMM)

// ---------------- scratch (static device globals; no allocation) ----------------
__device__ float g_q[QL * HID];          // Q projection (pre-RoPE, f32)
__device__ float g_kn[QL * NKVH * HD];   // new K projection (pre-RoPE)
__device__ float g_vn[QL * NKVH * HD];   // new V projection
__device__ float g_v[NKVH * KLEN * HD];  // full V (f32, for transpose)

// GEMM triplet operands (proven R7-R14 path, bf16 compensated)
__device__ __nv_bfloat16 g_x3[QL * K3];
__device__ __nv_bfloat16 g_w3[2048 * K3];
__device__ __nv_bfloat16 g_wo3[HID * K3];
__device__ __nv_bfloat16 g_at3[QL * K3];

// attention fp16 operands
__device__ __half g_qf[NH * QL * HD];        // RoPE'd Q, f16
__device__ __half g_kf[NKVH * KLEN * HD];    // full K, f16
__device__ __half g_vthf[NKVH * HD * KLEN];  // V^T hi (f16): [kv][d][pos]
__device__ __half g_vtlf[NKVH * HD * KLEN];  // V^T lo (f16 residual)

// ---------------- helpers ----------------
__device__ __forceinline__ uint32_t smem_u32(const void* p) {
    uint32_t a;
    asm("{ .reg .u64 t; cvta.to.shared.u64 t, %1; cvt.u32.u64 %0, t; }" : "=r"(a) : "l"(p));
    return a;
}
#define SWZ128(off) ((off) ^ (((off) >> 3) & 0x70))

__device__ __forceinline__ void ldsm4(uint32_t* r, uint32_t addr) {
    asm volatile("ldmatrix.sync.aligned.m8n8.x4.shared.b16 {%0,%1,%2,%3}, [%4];"
        : "=r"(r[0]), "=r"(r[1]), "=r"(r[2]), "=r"(r[3]) : "r"(addr));
}
__device__ __forceinline__ void mma16816(float* d, const uint32_t* a, const uint32_t* b) {
    asm volatile("mma.sync.aligned.m16n8k16.row.col.f32.bf16.bf16.f32 "
        "{%0,%1,%2,%3},{%4,%5,%6,%7},{%8,%9},{%0,%1,%2,%3};"
        : "+f"(d[0]), "+f"(d[1]), "+f"(d[2]), "+f"(d[3])
        : "r"(a[0]), "r"(a[1]), "r"(a[2]), "r"(a[3]), "r"(b[0]), "r"(b[1]));
}
__device__ __forceinline__ void mma16816h(float* d, const uint32_t* a, const uint32_t* b) {
    asm volatile("mma.sync.aligned.m16n8k16.row.col.f32.f16.f16.f32 "
        "{%0,%1,%2,%3},{%4,%5,%6,%7},{%8,%9},{%0,%1,%2,%3};"
        : "+f"(d[0]), "+f"(d[1]), "+f"(d[2]), "+f"(d[3])
        : "r"(a[0]), "r"(a[1]), "r"(a[2]), "r"(a[3]), "r"(b[0]), "r"(b[1]));
}
__device__ __forceinline__ void cp_async16(uint32_t saddr, const void* gptr) {
    asm volatile("cp.async.cg.shared.global [%0], [%1], 16;"
        :: "r"(saddr), "l"((size_t)__cvta_generic_to_global(gptr)) : "memory");
}
__device__ __forceinline__ void cp_commit() { asm volatile("cp.async.commit_group;" ::: "memory"); }
__device__ __forceinline__ void cp_wait0()  { asm volatile("cp.async.wait_group 0;" ::: "memory"); }
__device__ __forceinline__ void cp_wait1()  { asm volatile("cp.async.wait_group 1;" ::: "memory"); }

__device__ __forceinline__ void split2(float v, __nv_bfloat16& h, __nv_bfloat16& l) {
    h = __float2bfloat16(v);
    l = __float2bfloat16(v - __bfloat162float(h));
}
__device__ __forceinline__ uint32_t bfpack(__nv_bfloat16 a, __nv_bfloat16 b) {
    return (uint32_t)__bfloat16_as_ushort(a) | ((uint32_t)__bfloat16_as_ushort(b) << 16);
}
__device__ __forceinline__ uint32_t hpack(__half a, __half b) {
    return (uint32_t)__half_as_ushort(a) | ((uint32_t)__half_as_ushort(b) << 16);
}

// ================= conversion kernels (GEMM operands, unchanged) =================
__global__ void conv_x3_kernel(const float* __restrict__ src) {
    const int i = blockIdx.x * blockDim.x + threadIdx.x;
    const int m = i / HID, k = i % HID;
    __nv_bfloat16 h, l;
    split2(src[i], h, l);
    __nv_bfloat16* p = g_x3 + (ull)m * K3 + 3 * k;
    p[0] = h; p[1] = h; p[2] = l;
}

__global__ void conv_wqkv3_kernel(const float* __restrict__ Wq,
                                  const float* __restrict__ Wk,
                                  const float* __restrict__ Wv) {
    __shared__ float t[32][33];
    const int n0 = blockIdx.x * 32, k0 = blockIdx.y * 32;
    const int tx = threadIdx.x, ty = threadIdx.y;
    const float* W; int nb, ld;
    if (n0 < 1536)      { W = Wq; nb = n0;        ld = HID; }
    else if (n0 < 1792) { W = Wk; nb = n0 - 1536; ld = NKVH * HD; }
    else                { W = Wv; nb = n0 - 1792; ld = NKVH * HD; }
    for (int r = ty; r < 32; r += 8)
        t[r][tx] = W[(ull)(k0 + r) * ld + nb + tx];
    __syncthreads();
    for (int r = ty; r < 32; r += 8) {
        __nv_bfloat16 h, l;
        split2(t[tx][r], h, l);
        __nv_bfloat16* p = g_w3 + (ull)(n0 + r) * K3 + 3 * (k0 + tx);
        p[0] = h; p[1] = l; p[2] = h;
    }
}

__global__ void conv_wo3_kernel(const float* __restrict__ Wo) {
    __shared__ float t[32][33];
    const int n0 = blockIdx.x * 32, k0 = blockIdx.y * 32;
    const int tx = threadIdx.x, ty = threadIdx.y;
    for (int r = ty; r < 32; r += 8)
        t[r][tx] = Wo[(ull)(k0 + r) * HID + n0 + tx];
    __syncthreads();
    for (int r = ty; r < 32; r += 8) {
        __nv_bfloat16 h, l;
        split2(t[tx][r], h, l);
        __nv_bfloat16* p = g_wo3 + (ull)(n0 + r) * K3 + 3 * (k0 + tx);
        p[0] = h; p[1] = l; p[2] = h;
    }
}

// ================= HMMA GEMM: CTA tile 128x256, warp tile 64x64 (R14) =================
#define CHK     64
#define NCHUNK  (K3 / CHK)          // 72
#define A_TB    16384
#define B_TB    32768
#define BUF_TB  (A_TB + B_TB)
#define NBUF    3
#define GEMM_SMEM (NBUF * BUF_TB)   // 147456

__global__ __launch_bounds__(256, 1) void hmma_gemm_kernel(
    int mode, float* __restrict__ outp,
    const float* __restrict__ bq, const float* __restrict__ bk, const float* __restrict__ bv)
{
    extern __shared__ __align__(1024) char dynsm[];
    const uint32_t sbase = smem_u32(dynsm);
    const int tid  = threadIdx.x;
    const int lane = tid & 31;
    const int wid  = tid >> 5;
    const int wm   = wid >> 2;
    const int wn   = wid & 3;
    const int m0   = blockIdx.y * 128;
    const int n0   = blockIdx.x * 256;

    const __nv_bfloat16* __restrict__ A3 = (mode == 0) ? g_x3 : g_at3;
    const __nv_bfloat16* __restrict__ B3 = (mode == 0) ? g_w3 : g_wo3;

    float d[4][8][4];
#pragma unroll
    for (int mi = 0; mi < 4; mi++)
#pragma unroll
        for (int ni = 0; ni < 8; ni++)
#pragma unroll
            for (int r = 0; r < 4; r++) d[mi][ni][r] = 0.f;

    const int lr = tid >> 3;
    const int lg = tid & 7;

#pragma unroll
    for (int pc = 0; pc < 2; pc++) {
        const uint32_t sA = sbase + pc * BUF_TB, sB = sA + A_TB;
        const int k0 = pc * CHK;
#pragma unroll
        for (int it = 0; it < 4; it++) {
            const int r = lr + it * 32;
            const uint32_t so = SWZ128((uint32_t)(r * 128 + lg * 16));
            cp_async16(sA + so, A3 + (ull)(m0 + r) * K3 + k0 + lg * 8);
        }
#pragma unroll
        for (int it = 0; it < 8; it++) {
            const int r = lr + it * 32;
            const uint32_t so = SWZ128((uint32_t)(r * 128 + lg * 16));
            cp_async16(sB + so, B3 + (ull)(n0 + r) * K3 + k0 + lg * 8);
        }
        cp_commit();
    }

    const int arow = wm * 64 + (lane & 15);
    const int acol = (lane & 16) ? 16 : 0;
    const int brow = wn * 64 + (lane & 7) + ((lane & 16) ? 8 : 0);
    const int bcol = (lane & 8) ? 16 : 0;

    int ldbuf = 2;
    for (int c = 0; c < NCHUNK; c++) {
        cp_wait1();
        __syncthreads();
        if (c + 2 < NCHUNK) {
            const uint32_t sA = sbase + (uint32_t)ldbuf * BUF_TB, sB = sA + A_TB;
            const int k0 = (c + 2) * CHK;
#pragma unroll
            for (int it = 0; it < 4; it++) {
                const int r = lr + it * 32;
                const uint32_t so = SWZ128((uint32_t)(r * 128 + lg * 16));
                cp_async16(sA + so, A3 + (ull)(m0 + r) * K3 + k0 + lg * 8);
            }
#pragma unroll
            for (int it = 0; it < 8; it++) {
                const int r = lr + it * 32;
                const uint32_t so = SWZ128((uint32_t)(r * 128 + lg * 16));
                cp_async16(sB + so, B3 + (ull)(n0 + r) * K3 + k0 + lg * 8);
            }
            cp_commit();
            if (++ldbuf == NBUF) ldbuf = 0;
        }
        const uint32_t cb = (uint32_t)(c % NBUF) * BUF_TB;
        const uint32_t sA = sbase + cb, sB = sbase + cb + A_TB;
#pragma unroll
        for (int kk = 0; kk < 4; kk++) {
            uint32_t a[4][4], bb[8][2];
#pragma unroll
            for (int mi = 0; mi < 4; mi++)
                ldsm4(a[mi], sA + SWZ128((uint32_t)((arow + mi * 16) * 128 + kk * 32 + acol)));
#pragma unroll
            for (int nj = 0; nj < 4; nj++) {
                uint32_t t4[4];
                ldsm4(t4, sB + SWZ128((uint32_t)((brow + nj * 16) * 128 + kk * 32 + bcol)));
                bb[nj * 2][0] = t4[0]; bb[nj * 2][1] = t4[1];
                bb[nj * 2 + 1][0] = t4[2]; bb[nj * 2 + 1][1] = t4[3];
            }
#pragma unroll
            for (int mi = 0; mi < 4; mi++)
#pragma unroll
                for (int ni = 0; ni < 8; ni++)
                    mma16816(d[mi][ni], a[mi], bb[ni]);
        }
        __syncthreads();
    }

    float* dst; int ldc; const float* bias; int coff;
    if (mode == 1)             { dst = outp; ldc = HID;       bias = nullptr; coff = n0; }
    else if (blockIdx.x < 6)   { dst = g_q;  ldc = HID;       bias = bq + n0; coff = n0; }
    else if (blockIdx.x == 6)  { dst = g_kn; ldc = NKVH * HD; bias = bk;      coff = 0; }
    else                       { dst = g_vn; ldc = NKVH * HD; bias = bv;      coff = 0; }

#pragma unroll
    for (int mi = 0; mi < 4; mi++) {
        const int r0 = m0 + wm * 64 + mi * 16 + (lane >> 2);
#pragma unroll
        for (int ni = 0; ni < 8; ni++) {
            const int cl = wn * 64 + ni * 8 + (lane & 3) * 2;
            float b0 = 0.f, b1 = 0.f;
            if (bias) { b0 = bias[cl]; b1 = bias[cl + 1]; }
            float2 v0 = { d[mi][ni][0] + b0, d[mi][ni][1] + b1 };
            float2 v1 = { d[mi][ni][2] + b0, d[mi][ni][3] + b1 };
            *(float2*)(dst + (ull)r0 * ldc + coff + cl)       = v0;
            *(float2*)(dst + (ull)(r0 + 8) * ldc + coff + cl) = v1;
        }
    }
}

// ---------------- RoPE on Q -> f16 ----------------
__global__ void rope_q_kernel(const float* __restrict__ fcos, const float* __restrict__ fsin)
{
    const int t = blockIdx.x;
    const int h = threadIdx.x >> 6;
    const int i = threadIdx.x & 63;
    const float* q = g_q + (ull)t * HID + h * HD;
    const float c = fcos[t * 64 + i];
    const float s = fsin[t * 64 + i];
    const float x1 = q[i];
    const float x2 = q[i + 64];
    const ull base = ((ull)h * QL + t) * HD;
    g_qf[base + i]      = __float2half(x1 * c - x2 * s);
    g_qf[base + i + 64] = __float2half(x1 * s + x2 * c);
}

// ---------------- build full K (f16) + V (f32) ----------------
__global__ void build_kv_kernel(
    const float* __restrict__ k_hist, const float* __restrict__ v_hist,
    const float* __restrict__ fcos, const float* __restrict__ fsin)
{
    const int pos = blockIdx.x;
    const int kv = blockIdx.y;
    const int i = threadIdx.x;
    float* vd = g_v + ((ull)(kv * KLEN + pos)) * HD;
    float k1, k2;
    if (pos < HISTL) {
        const float* ks = k_hist + ((ull)pos * NKVH + kv) * HD;
        const float* vs = v_hist + ((ull)pos * NKVH + kv) * HD;
        k1 = ks[i]; k2 = ks[i + 64];
        vd[i] = vs[i]; vd[i + 64] = vs[i + 64];
    } else {
        const int t = pos - HISTL;
        const float* ks = g_kn + (ull)t * (NKVH * HD) + kv * HD;
        const float* vs = g_vn + (ull)t * (NKVH * HD) + kv * HD;
        const float c = fcos[t * 64 + i];
        const float s = fsin[t * 64 + i];
        const float x1 = ks[i];
        const float x2 = ks[i + 64];
        k1 = x1 * c - x2 * s;
        k2 = x1 * s + x2 * c;
        vd[i] = vs[i]; vd[i + 64] = vs[i + 64];
    }
    const ull base = ((ull)(kv * KLEN + pos)) * HD;
    g_kf[base + i]      = __float2half(k1);
    g_kf[base + i + 64] = __float2half(k2);
}

// ---------------- transpose V -> V^T f16 hi/lo planes ----------------
__global__ void vt_kernel() {
    __shared__ float t[32][33];
    const int pos0 = blockIdx.x * 32, d0 = blockIdx.y * 32, kv = blockIdx.z;
    const int tx = threadIdx.x, ty = threadIdx.y;
    for (int r = ty; r < 32; r += 8)
        t[r][tx] = g_v[((ull)(kv * KLEN + pos0 + r)) * HD + d0 + tx];
    __syncthreads();
    for (int r = ty; r < 32; r += 8) {
        const float v = t[tx][r];
        const __half h = __float2half(v);
        const __half l = __float2half(v - __half2float(h));
        const ull o = ((ull)(kv * HD + d0 + r)) * KLEN + pos0 + tx;
        g_vthf[o] = h; g_vtlf[o] = l;
    }
}

// ================= fp16 HMMA flash attention: 64q x 64k =================
// QK: single pass f16. PV: 2 passes (P f16) x (Vh, Vl f16 hi/lo).
#define QSTR 272            // Q/K row stride (128 f16 = 256B + 16 pad)
#define VSTR 144            // V^T / P row stride (64 f16 = 128B + 16 pad)
#define OFF_Q  0            // 64 x 272 = 17408
#define OFF_K  17408
#define OFF_V  34816        // 2 bufs x (Vh 18432 + Vl 18432) = 73728
#define VBUF_B 36864
#define OFF_P  108544       // 64 x 144 = 9216
#define OFF_RS 117760
#define ATT_SMEM 118784

__global__ __launch_bounds__(256, 1) void attention_kernel()
{
    extern __shared__ __align__(1024) char asmem[];
    const uint32_t sb = smem_u32(asmem);
    const int h  = blockIdx.x;
    const int qb = 31 - blockIdx.y;
    const int kvh = h / GRP;
    const int q0 = qb * 64;
    const int tid = threadIdx.x;
    const int lane = tid & 31;
    const int wid = tid >> 5;
    const int wm = wid >> 2;      // 0..1
    const int wn = wid & 3;       // 0..3
    const int n_tiles = qb + 33;

    const __half* Qg  = g_qf   + ((ull)h * QL + q0) * HD;
    const __half* Kg  = g_kf   + ((ull)kvh * KLEN) * HD;
    const __half* Vgh = g_vthf + ((ull)kvh * HD) * KLEN;
    const __half* Vgl = g_vtlf + ((ull)kvh * HD) * KLEN;

    // ---- prologue: Q + K[0] + V[0] planes ----
    for (int u = tid; u < 64 * 16; u += 256) {
        const int r = u >> 4, c = u & 15;
        cp_async16(sb + OFF_Q + r * QSTR + c * 16, Qg + (ull)r * HD + c * 8);
        cp_async16(sb + OFF_K + r * QSTR + c * 16, Kg + (ull)r * HD + c * 8);
    }
    for (int u = tid; u < 128 * 8; u += 256) {
        const int r = u >> 3, c = u & 7;
        cp_async16(sb + OFF_V + r * VSTR + c * 16,         Vgh + (ull)r * KLEN + c * 8);
        cp_async16(sb + OFF_V + 18432 + r * VSTR + c * 16, Vgl + (ull)r * KLEN + c * 8);
    }
    cp_commit();

    float accO[2][4][4];
    float psum[2][2];
#pragma unroll
    for (int mi = 0; mi < 2; mi++) {
#pragma unroll
        for (int hf = 0; hf < 2; hf++) psum[mi][hf] = 0.f;
#pragma unroll
        for (int ni = 0; ni < 4; ni++)
#pragma unroll
            for (int r = 0; r < 4; r++) accO[mi][ni][r] = 0.f;
    }

    const int arow = wm * 32 + (lane & 15);
    const int acol = (lane & 16) ? 16 : 0;
    const int kbrow = wn * 16 + (lane & 7) + ((lane & 16) ? 8 : 0);
    const int vbrow = wn * 32 + (lane & 7) + ((lane & 16) ? 8 : 0);
    const int kbcol = (lane & 8) ? 16 : 0;

    // ---- load Q fragments ONCE for the whole block ----
    cp_wait0();
    __syncthreads();
    uint32_t qf[8][2][4];
#pragma unroll
    for (int kk = 0; kk < 8; kk++) {
        ldsm4(qf[kk][0], sb + OFF_Q + (uint32_t)(arow * QSTR + kk * 32 + acol));
        ldsm4(qf[kk][1], sb + OFF_Q + (uint32_t)((arow + 16) * QSTR + kk * 32 + acol));
    }

    for (int kt = 0; kt < n_tiles; kt++) {
        cp_wait0();
        __syncthreads();           // tile data ready; prev PV done

        // ==== S = Q K^T, single fp16 pass ====
        float S[2][2][4];
#pragma unroll
        for (int mi = 0; mi < 2; mi++)
#pragma unroll
            for (int nf = 0; nf < 2; nf++)
#pragma unroll
                for (int r = 0; r < 4; r++) S[mi][nf][r] = 0.f;

#pragma unroll
        for (int kk = 0; kk < 8; kk++) {
            uint32_t kfr[4];
            ldsm4(kfr, sb + OFF_K + (uint32_t)(kbrow * QSTR + kk * 32 + kbcol));
            mma16816h(S[0][0], qf[kk][0], &kfr[0]);
            mma16816h(S[0][1], qf[kk][0], &kfr[2]);
            mma16816h(S[1][0], qf[kk][1], &kfr[0]);
            mma16816h(S[1][1], qf[kk][1], &kfr[2]);
        }
        __syncthreads();           // QK ldsm done -> K SMEM reusable

        // ---- prefetch next tile's K (+V alt buffer) ----
        if (kt + 1 < n_tiles) {
            const int kb2 = (kt + 1) * 64;
            for (int u = tid; u < 64 * 16; u += 256) {
                const int r = u >> 4, c = u & 15;
                cp_async16(sb + OFF_K + r * QSTR + c * 16, Kg + (ull)(kb2 + r) * HD + c * 8);
            }
            const uint32_t vbuf = sb + OFF_V + ((kt + 1) & 1) * VBUF_B;
            for (int u = tid; u < 128 * 8; u += 256) {
                const int r = u >> 3, c = u & 7;
                cp_async16(vbuf + r * VSTR + c * 16,         Vgh + (ull)r * KLEN + kb2 + c * 8);
                cp_async16(vbuf + 18432 + r * VSTR + c * 16, Vgl + (ull)r * KLEN + kb2 + c * 8);
            }
            cp_commit();
        }

        // ---- scale + mask + exp + write P (f16) + partial sums ----
        const int kb = kt * 64;
        const bool maskt = (kt == qb + 32);
#pragma unroll
        for (int mi = 0; mi < 2; mi++)
#pragma unroll
            for (int nf = 0; nf < 2; nf++)
#pragma unroll
                for (int hf = 0; hf < 2; hf++) {
                    float s0 = S[mi][nf][hf * 2 + 0] * 0.08838834764831845f;
                    float s1 = S[mi][nf][hf * 2 + 1] * 0.08838834764831845f;
                    if (maskt) {
                        const int qg = q0 + wm * 32 + mi * 16 + (lane >> 2) + hf * 8;
                        const int kg = kb + wn * 16 + nf * 8 + (lane & 3) * 2;
                        if (kg > qg + HISTL)     s0 = -1e30f;
                        if (kg + 1 > qg + HISTL) s1 = -1e30f;
                    }
                    const float p0 = __expf(s0);
                    const float p1 = __expf(s1);
                    psum[mi][hf] += p0 + p1;
                    const int row = wm * 32 + mi * 16 + hf * 8 + (lane >> 2);
                    const int c2 = wn * 16 + nf * 8 + (lane & 3) * 2;
                    *(uint32_t*)(asmem + OFF_P + row * VSTR + 2 * c2) =
                        hpack(__float2half(p0), __float2half(p1));
                }
        __syncthreads();           // P ready

        // ==== O += P @ V^T, 2 passes (P held; Vh then Vl) ====
        const uint32_t sP  = sb + OFF_P;
        const uint32_t sVH = sb + OFF_V + (kt & 1) * VBUF_B;
        const uint32_t sVL = sVH + 18432;

        uint32_t pf[4][2][4];
        // pass 1: P * Vh
#pragma unroll
        for (int kk = 0; kk < 4; kk++) {
            ldsm4(pf[kk][0], sP + (uint32_t)(arow * VSTR + kk * 32 + acol));
            ldsm4(pf[kk][1], sP + (uint32_t)((arow + 16) * VSTR + kk * 32 + acol));
            uint32_t v0[4], v1[4];
            ldsm4(v0, sVH + (uint32_t)(vbrow * VSTR + kk * 32 + kbcol));
            ldsm4(v1, sVH + (uint32_t)((vbrow + 16) * VSTR + kk * 32 + kbcol));
            mma16816h(accO[0][0], pf[kk][0], &v0[0]);
            mma16816h(accO[0][1], pf[kk][0], &v0[2]);
            mma16816h(accO[0][2], pf[kk][0], &v1[0]);
            mma16816h(accO[0][3], pf[kk][0], &v1[2]);
            mma16816h(accO[1][0], pf[kk][1], &v0[0]);
            mma16816h(accO[1][1], pf[kk][1], &v0[2]);
            mma16816h(accO[1][2], pf[kk][1], &v1[0]);
            mma16816h(accO[1][3], pf[kk][1], &v1[2]);
        }
        // pass 2: P * Vl (P held)
#pragma unroll
        for (int kk = 0; kk < 4; kk++) {
            uint32_t v0[4], v1[4];
            ldsm4(v0, sVL + (uint32_t)(vbrow * VSTR + kk * 32 + kbcol));
            ldsm4(v1, sVL + (uint32_t)((vbrow + 16) * VSTR + kk * 32 + kbcol));
            mma16816h(accO[0][0], pf[kk][0], &v0[0]);
            mma16816h(accO[0][1], pf[kk][0], &v0[2]);
            mma16816h(accO[0][2], pf[kk][0], &v1[0]);
            mma16816h(accO[0][3], pf[kk][0], &v1[2]);
            mma16816h(accO[1][0], pf[kk][1], &v0[0]);
            mma16816h(accO[1][1], pf[kk][1], &v0[2]);
            mma16816h(accO[1][2], pf[kk][1], &v1[0]);
            mma16816h(accO[1][3], pf[kk][1], &v1[2]);
        }
    }

    // ---- one-time row-sum reduction ----
    float* rs = (float*)(asmem + OFF_RS);
#pragma unroll
    for (int mi = 0; mi < 2; mi++)
#pragma unroll
        for (int hf = 0; hf < 2; hf++) {
            float v = psum[mi][hf];
            v += __shfl_xor_sync(0xffffffffu, v, 1);
            v += __shfl_xor_sync(0xffffffffu, v, 2);
            psum[mi][hf] = v;
        }
    __syncthreads();
    if ((lane & 3) == 0) {
#pragma unroll
        for (int mi = 0; mi < 2; mi++)
#pragma unroll
            for (int hf = 0; hf < 2; hf++)
                rs[wn * 64 + wm * 32 + mi * 16 + hf * 8 + (lane >> 2)] = psum[mi][hf];
    }
    __syncthreads();

    // ---- epilogue: normalize, write g_at3 triplets (A-side h,h,l for O GEMM) ----
#pragma unroll
    for (int mi = 0; mi < 2; mi++) {
#pragma unroll
        for (int hf = 0; hf < 2; hf++) {
            const int lrow = wm * 32 + mi * 16 + hf * 8 + (lane >> 2);
            const float lsum = rs[0 * 64 + lrow] + rs[1 * 64 + lrow]
                             + rs[2 * 64 + lrow] + rs[3 * 64 + lrow];
            const float inv = 1.f / lsum;
            const int row = q0 + lrow;
#pragma unroll
            for (int ni = 0; ni < 4; ni++) {
                const int dcol = wn * 32 + ni * 8 + (lane & 3) * 2;
                const float v0 = accO[mi][ni][hf * 2 + 0] * inv;
                const float v1 = accO[mi][ni][hf * 2 + 1] * inv;
                __nv_bfloat16 h0, l0, h1, l1;
                split2(v0, h0, l0); split2(v1, h1, l1);
                uint32_t* dp = (uint32_t*)(g_at3 + (ull)row * K3 + 3 * (h * HD + dcol));
                dp[0] = bfpack(h0, h0);
                dp[1] = bfpack(l0, h1);
                dp[2] = bfpack(h1, l1);
            }
        }
    }
}

// ---------------- launch ----------------
extern "C" void kernel_launch(void* const* d_in, const int* in_sizes, int n_in,
                              void* d_out, int out_size)
{
    const float* x     = (const float*)d_in[0];
    const float* Wq    = (const float*)d_in[1];
    const float* bq    = (const float*)d_in[2];
    const float* Wk    = (const float*)d_in[3];
    const float* bk    = (const float*)d_in[4];
    const float* Wv    = (const float*)d_in[5];
    const float* bv    = (const float*)d_in[6];
    const float* Wo    = (const float*)d_in[7];
    const float* khist = (const float*)d_in[8];
    const float* vhist = (const float*)d_in[9];
    const float* fcos  = (const float*)d_in[10];
    const float* fsin  = (const float*)d_in[11];
    float* out = (float*)d_out;

    cudaFuncSetAttribute(attention_kernel,
                         cudaFuncAttributeMaxDynamicSharedMemorySize, ATT_SMEM);
    cudaFuncSetAttribute(hmma_gemm_kernel,
                         cudaFuncAttributeMaxDynamicSharedMemorySize, GEMM_SMEM);

    conv_x3_kernel<<<QL * HID / 256, 256>>>(x);
    conv_wqkv3_kernel<<<dim3(64, 48), dim3(32, 8)>>>(Wq, Wk, Wv);
    conv_wo3_kernel<<<dim3(48, 48), dim3(32, 8)>>>(Wo);

    // QKV projection: N=2048 in 256-col tiles -> grid (8, 16)
    hmma_gemm_kernel<<<dim3(8, 16), 256, GEMM_SMEM>>>(0, nullptr, bq, bk, bv);

    rope_q_kernel<<<QL, NH * 64>>>(fcos, fsin);
    build_kv_kernel<<<dim3(KLEN, NKVH), 64>>>(khist, vhist, fcos, fsin);
    vt_kernel<<<dim3(KLEN / 32, HD / 32, NKVH), dim3(32, 8)>>>();

    attention_kernel<<<dim3(NH, 32), 256, ATT_SMEM>>>();

    // O projection: N=1536 in 256-col tiles -> grid (6, 16)
    hmma_gemm_kernel<<<dim3(6, 16), 256, GEMM_SMEM>>>(1, out, nullptr, nullptr, nullptr);
}